// round 2
// baseline (speedup 1.0000x reference)
#include <cuda_runtime.h>
#include <math.h>

#define NUM_STEPS 30
#define NKEYS 65536          // 2 batches x 15-bit morton
#define SCAN_BLOCKS 64       // 64 x 1024 = NKEYS
#define PERM_CAP (1 << 19)   // 524288 >= 280000

// ---- static device scratch (no allocation allowed) ----
__device__ float g_inv_affine[8 * 16];
__device__ int g_cnt[NKEYS];
__device__ int g_off[NKEYS];
__device__ int g_bsum[SCAN_BLOCKS];
__device__ int g_perm[PERM_CAP];

// ---------------------------------------------------------------------------
// affine inverse (once per launch, tiny)
// ---------------------------------------------------------------------------
__global__ void invert_affine_kernel(const float* __restrict__ affine, int B) {
    int b = threadIdx.x;
    if (b >= B) return;
    double m[4][8];
    #pragma unroll
    for (int i = 0; i < 4; i++) {
        #pragma unroll
        for (int j = 0; j < 4; j++) m[i][j] = (double)affine[b * 16 + i * 4 + j];
        #pragma unroll
        for (int j = 0; j < 4; j++) m[i][4 + j] = (i == j) ? 1.0 : 0.0;
    }
    for (int col = 0; col < 4; col++) {
        int piv = col;
        double best = fabs(m[col][col]);
        for (int r = col + 1; r < 4; r++) {
            double v = fabs(m[r][col]);
            if (v > best) { best = v; piv = r; }
        }
        if (piv != col)
            for (int j = 0; j < 8; j++) { double t = m[col][j]; m[col][j] = m[piv][j]; m[piv][j] = t; }
        double inv = 1.0 / m[col][col];
        for (int j = 0; j < 8; j++) m[col][j] *= inv;
        for (int r = 0; r < 4; r++) {
            if (r == col) continue;
            double f = m[r][col];
            for (int j = 0; j < 8; j++) m[r][j] -= f * m[col][j];
        }
    }
    #pragma unroll
    for (int i = 0; i < 4; i++)
        #pragma unroll
        for (int j = 0; j < 4; j++)
            g_inv_affine[b * 16 + i * 4 + j] = (float)m[i][4 + j];
}

// ---------------------------------------------------------------------------
// bucket key: morton code of 8-voxel cell of the affine-transformed position
// ---------------------------------------------------------------------------
__device__ __forceinline__ unsigned spread3(unsigned x) {
    // 5-bit value -> bits at positions 0,3,6,9,12
    return (x & 1u) | ((x & 2u) << 2) | ((x & 4u) << 4) | ((x & 8u) << 6) | ((x & 16u) << 8);
}

__device__ __forceinline__ int compute_key(const float* __restrict__ verts,
                                           const float* __restrict__ affine,
                                           int b, int n, int N,
                                           float dmax, float hmax, float wmax) {
    const float* A = affine + b * 16;
    size_t vb = ((size_t)b * N + n) * 3;
    float vx = verts[vb + 0], vy = verts[vb + 1], vz = verts[vb + 2];
    float px = A[0] * vx + A[1] * vy + A[2]  * vz + A[3];
    float py = A[4] * vx + A[5] * vy + A[6]  * vz + A[7];
    float pz = A[8] * vx + A[9] * vy + A[10] * vz + A[11];
    float pd = fminf(fmaxf(px, 0.0f), dmax);
    float ph = fminf(fmaxf(py, 0.0f), hmax);
    float pw = fminf(fmaxf(pz, 0.0f), wmax);
    unsigned cd = ((unsigned)(int)pd) >> 3;
    unsigned ch = ((unsigned)(int)ph) >> 3;
    unsigned cw = ((unsigned)(int)pw) >> 3;
    unsigned m = (spread3(cd) << 2) | (spread3(ch) << 1) | spread3(cw);
    return b * 32768 + (int)m;
}

__global__ void count_kernel(const float* __restrict__ verts,
                             const float* __restrict__ affine,
                             int B, int N, float dmax, float hmax, float wmax) {
    int gid = blockIdx.x * blockDim.x + threadIdx.x;
    long long total = (long long)B * N;
    if (gid >= total) return;
    int b = gid / N, n = gid % N;
    int key = compute_key(verts, affine, b, n, N, dmax, hmax, wmax);
    atomicAdd(&g_cnt[key], 1);
}

__global__ void scan1_kernel() {
    __shared__ int sh[1024];
    int g = blockIdx.x * 1024 + threadIdx.x;
    int v = g_cnt[g];
    sh[threadIdx.x] = v;
    __syncthreads();
    for (int off = 1; off < 1024; off <<= 1) {
        int t = (threadIdx.x >= off) ? sh[threadIdx.x - off] : 0;
        __syncthreads();
        sh[threadIdx.x] += t;
        __syncthreads();
    }
    g_off[g] = sh[threadIdx.x] - v;  // exclusive
    if (threadIdx.x == 1023) g_bsum[blockIdx.x] = sh[1023];
}

__global__ void scan2_kernel() {
    __shared__ int sh[SCAN_BLOCKS];
    int t = threadIdx.x;
    int v = g_bsum[t];
    sh[t] = v;
    __syncthreads();
    for (int off = 1; off < SCAN_BLOCKS; off <<= 1) {
        int x = (t >= off) ? sh[t - off] : 0;
        __syncthreads();
        sh[t] += x;
        __syncthreads();
    }
    g_bsum[t] = sh[t] - v;  // exclusive block offsets
}

__global__ void scan3_kernel() {
    int g = blockIdx.x * 1024 + threadIdx.x;
    g_off[g] += g_bsum[blockIdx.x];
}

__global__ void scatter_kernel(const float* __restrict__ verts,
                               const float* __restrict__ affine,
                               int B, int N, float dmax, float hmax, float wmax) {
    int gid = blockIdx.x * blockDim.x + threadIdx.x;
    long long total = (long long)B * N;
    if (gid >= total) return;
    int b = gid / N, n = gid % N;
    int key = compute_key(verts, affine, b, n, N, dmax, hmax, wmax);
    int pos = atomicAdd(&g_off[key], 1);
    g_perm[pos] = gid;
}

// ---------------------------------------------------------------------------
// main integration kernel
// ---------------------------------------------------------------------------
__global__ __launch_bounds__(256)
void deform_kernel(const float* __restrict__ verts,
                   const float* __restrict__ affine,
                   const float* __restrict__ flow,
                   float* __restrict__ out,
                   int B, int N, int D, int H, int W, int use_perm)
{
    int gid = blockIdx.x * blockDim.x + threadIdx.x;
    long long total = (long long)B * N;
    if (gid >= total) return;
    int pt = use_perm ? g_perm[gid] : gid;
    int b = pt / N;
    int n = pt % N;

    // ---- affine transform of homogeneous vertex ----
    const float* A = affine + b * 16;
    size_t vbase = ((size_t)b * N + n) * 3;
    float vx = verts[vbase + 0];
    float vy = verts[vbase + 1];
    float vz = verts[vbase + 2];

    float px = A[0] * vx + A[1] * vy + A[2]  * vz + A[3];
    float py = A[4] * vx + A[5] * vy + A[6]  * vz + A[7];
    float pz = A[8] * vx + A[9] * vy + A[10] * vz + A[11];

    // ---- Euler integration with per-thread corner cache (32-bit offsets) ----
    const int HW  = H * W;
    const int DHW = D * HW;
    const float* base = flow + (size_t)b * 3 * (size_t)DHW;
    const float scale = 1.0f / (float)NUM_STEPS;
    const float dmax = (float)(D - 1), hmax = (float)(H - 1), wmax = (float)(W - 1);

    float xd = px, xh = py, xw = pz;
    int cell = -1;                 // packed (d0<<20)|(h0<<10)|w0
    float c[3][8];

    #pragma unroll 1
    for (int s = 0; s < NUM_STEPS; s++) {
        float pdc = fminf(fmaxf(xd, 0.0f), dmax);
        float phc = fminf(fmaxf(xh, 0.0f), hmax);
        float pwc = fminf(fmaxf(xw, 0.0f), wmax);
        float fd0 = floorf(pdc), fh0 = floorf(phc), fw0 = floorf(pwc);
        int d0 = (int)fd0, h0 = (int)fh0, w0 = (int)fw0;
        float fd = pdc - fd0, fh = phc - fh0, fw = pwc - fw0;

        int ncell = (d0 << 20) | (h0 << 10) | w0;
        if (ncell != cell) {
            cell = ncell;
            int d1 = min(d0 + 1, D - 1);
            int h1 = min(h0 + 1, H - 1);
            int w1 = min(w0 + 1, W - 1);
            int rd0 = d0 * HW, rd1 = d1 * HW;
            int rh0 = h0 * W,  rh1 = h1 * W;
            int o000 = rd0 + rh0 + w0;
            int o001 = rd0 + rh0 + w1;
            int o010 = rd0 + rh1 + w0;
            int o011 = rd0 + rh1 + w1;
            int o100 = rd1 + rh0 + w0;
            int o101 = rd1 + rh0 + w1;
            int o110 = rd1 + rh1 + w0;
            int o111 = rd1 + rh1 + w1;
            #pragma unroll
            for (int cc = 0; cc < 3; cc++) {
                const float* p = base + cc * DHW;
                c[cc][0] = __ldg(p + o000);
                c[cc][1] = __ldg(p + o001);
                c[cc][2] = __ldg(p + o010);
                c[cc][3] = __ldg(p + o011);
                c[cc][4] = __ldg(p + o100);
                c[cc][5] = __ldg(p + o101);
                c[cc][6] = __ldg(p + o110);
                c[cc][7] = __ldg(p + o111);
            }
        }

        float omfw = 1.0f - fw;
        float omfh = 1.0f - fh;
        float omfd = 1.0f - fd;
        float samp[3];
        #pragma unroll
        for (int cc = 0; cc < 3; cc++) {
            float c00 = c[cc][0] * omfw + c[cc][1] * fw;
            float c01 = c[cc][2] * omfw + c[cc][3] * fw;
            float c10 = c[cc][4] * omfw + c[cc][5] * fw;
            float c11 = c[cc][6] * omfw + c[cc][7] * fw;
            float c0  = c00 * omfh + c01 * fh;
            float c1  = c10 * omfh + c11 * fh;
            samp[cc]  = c0 * omfd + c1 * fd;
        }
        xd += samp[0] * scale;
        xh += samp[1] * scale;
        xw += samp[2] * scale;
    }

    // ---- outputs ----
    float fix = xd - px;
    float fiy = xh - py;
    float fiz = xw - pz;

    const float* Inv = g_inv_affine + b * 16;
    float ox = Inv[0] * xd + Inv[1] * xh + Inv[2]  * xw + Inv[3];
    float oy = Inv[4] * xd + Inv[5] * xh + Inv[6]  * xw + Inv[7];
    float oz = Inv[8] * xd + Inv[9] * xh + Inv[10] * xw + Inv[11];

    size_t pb = ((size_t)b * N + n) * 3;
    out[pb + 0] = ox;
    out[pb + 1] = oy;
    out[pb + 2] = oz;

    size_t fb = (size_t)B * N * 3 + ((size_t)b * 3) * (size_t)N + n;
    out[fb + 0 * (size_t)N] = fix;
    out[fb + 1 * (size_t)N] = fiy;
    out[fb + 2 * (size_t)N] = fiz;
}

extern "C" void kernel_launch(void* const* d_in, const int* in_sizes, int n_in,
                              void* d_out, int out_size) {
    const float* verts  = (const float*)d_in[0];
    const float* affine = (const float*)d_in[1];
    const float* flow   = (const float*)d_in[2];
    float* out = (float*)d_out;

    int B = in_sizes[1] / 16;
    int N = in_sizes[0] / (3 * B);
    long long dhw = (long long)in_sizes[2] / (3LL * B);
    int D = (int)llrint(cbrt((double)dhw));
    int H = D, W = D;
    float dmax = (float)(D - 1), hmax = (float)(H - 1), wmax = (float)(W - 1);

    long long total = (long long)B * N;
    int threads = 256;
    int blocks = (int)((total + threads - 1) / threads);

    // sorting only valid for D<=256 (5-bit cell coords) and within perm capacity
    int use_perm = (total <= PERM_CAP && D <= 256 && B <= 2) ? 1 : 0;

    if (use_perm) {
        void* cnt_ptr = nullptr;
        cudaGetSymbolAddress(&cnt_ptr, g_cnt);
        cudaMemsetAsync(cnt_ptr, 0, NKEYS * sizeof(int));
        count_kernel<<<blocks, threads>>>(verts, affine, B, N, dmax, hmax, wmax);
        scan1_kernel<<<SCAN_BLOCKS, 1024>>>();
        scan2_kernel<<<1, SCAN_BLOCKS>>>();
        scan3_kernel<<<SCAN_BLOCKS, 1024>>>();
        scatter_kernel<<<blocks, threads>>>(verts, affine, B, N, dmax, hmax, wmax);
    }

    invert_affine_kernel<<<1, 32>>>(affine, B);
    deform_kernel<<<blocks, threads>>>(verts, affine, flow, out,
                                       B, N, D, H, W, use_perm);
}